// round 1
// baseline (speedup 1.0000x reference)
#include <cuda_runtime.h>

#define NN 768
#define NA 192
#define NL 576
#define DD 128
#define HH 6
#define HD 768
#define NG 8
#define MM 96
#define PSZ (HD*NN)   // 768*768 per projection matrix

#define SCALE 0.08838834764831845f

// ---------------- device scratch (no allocations allowed) ----------------
__device__ float g_nodes[NN*DD];
__device__ int   g_inv[NN];
__device__ int   g_mem[NG*MM];
__device__ float g_p[3*PSZ];            // q,k,v projections (LN'd in place)
__device__ float g_s[NG*HH*MM*MM];      // softmaxed scores
__device__ float g_att[NN*HD];          // attention output
__device__ float g_r1[NN*DD];           // relu(ln(att @ Wo1^T))
__device__ float g_h[NN*DD];            // relu(ln(nodes@W1^T + r1@Wo2^T))

// ---------------- kernel 0: prep ----------------
__global__ __launch_bounds__(256) void k_prep(const float* __restrict__ agents,
                                              const int* __restrict__ agent_ids,
                                              const float* __restrict__ lanes,
                                              const int* __restrict__ lane_ids) {
    int idx = blockIdx.x * 256 + threadIdx.x;
    if (idx < NA*DD) g_nodes[idx] = agents[idx];
    int li = idx - NA*DD;
    if (li >= 0 && li < NL*DD) g_nodes[NA*DD + li] = lanes[li];
    if (idx < NA) {
        int n = agent_ids[idx];
        g_inv[n] = idx;
        g_mem[(idx/24)*MM + (idx%24)] = n;
    }
    if (idx < NL) {
        int n = NA + lane_ids[idx];
        g_inv[n] = NA + idx;
        g_mem[(idx/72)*MM + 24 + (idx%72)] = n;
    }
}

// ---------------- kernel 1: QKV GEMM  P = nodes @ W^T  (M=768, N=2304, K=128)
__global__ __launch_bounds__(256) void k_qkv(const float* __restrict__ Wq,
                                             const float* __restrict__ Wk,
                                             const float* __restrict__ Wv) {
    __shared__ float As[64][65];
    __shared__ float Bs[64][65];
    int m0  = blockIdx.x * 64;
    int sel = blockIdx.y / 12;
    int w0  = (blockIdx.y % 12) * 64;
    const float* W = sel == 0 ? Wq : (sel == 1 ? Wk : Wv);
    int tid = threadIdx.x;
    int tx = tid & 15, ty = tid >> 4;
    float acc[4][4] = {};
    for (int kc = 0; kc < 2; kc++) {
        int k0 = kc * 64;
#pragma unroll
        for (int i = 0; i < 4; i++) {
            int lin = tid + i*256;            // float4 index in 64x64 tile
            int row = lin >> 4, c4 = lin & 15;
            float4 v = *(const float4*)&g_nodes[(m0+row)*DD + k0 + c4*4];
            As[row][c4*4+0]=v.x; As[row][c4*4+1]=v.y; As[row][c4*4+2]=v.z; As[row][c4*4+3]=v.w;
            float4 u = *(const float4*)&W[(w0+row)*DD + k0 + c4*4];
            Bs[row][c4*4+0]=u.x; Bs[row][c4*4+1]=u.y; Bs[row][c4*4+2]=u.z; Bs[row][c4*4+3]=u.w;
        }
        __syncthreads();
#pragma unroll 8
        for (int k = 0; k < 64; k++) {
            float a[4], b[4];
#pragma unroll
            for (int i = 0; i < 4; i++) a[i] = As[ty + 16*i][k];
#pragma unroll
            for (int j = 0; j < 4; j++) b[j] = Bs[tx + 16*j][k];
#pragma unroll
            for (int i = 0; i < 4; i++)
#pragma unroll
                for (int j = 0; j < 4; j++) acc[i][j] += a[i]*b[j];
        }
        __syncthreads();
    }
    float* out = g_p + sel*PSZ;
#pragma unroll
    for (int i = 0; i < 4; i++)
#pragma unroll
        for (int j = 0; j < 4; j++)
            out[(m0 + ty + 16*i)*HD + w0 + tx + 16*j] = acc[i][j];
}

// ---------------- kernel 2: LayerNorm over HD=768 (in place; ReLU for V)
__global__ __launch_bounds__(256) void k_ln(const float* __restrict__ gq, const float* __restrict__ bq,
                                            const float* __restrict__ gk, const float* __restrict__ bk,
                                            const float* __restrict__ gv, const float* __restrict__ bv) {
    int row = blockIdx.x, sel = blockIdx.y;
    float* base = g_p + sel*PSZ + row*HD;
    const float* g = sel==0 ? gq : (sel==1 ? gk : gv);
    const float* b = sel==0 ? bq : (sel==1 ? bk : bv);
    int tid = threadIdx.x;
    float v[3]; float s = 0.f, s2 = 0.f;
#pragma unroll
    for (int i = 0; i < 3; i++) {
        v[i] = base[tid + 256*i];
        s += v[i]; s2 += v[i]*v[i];
    }
    __shared__ float rs[8], rs2[8];
#pragma unroll
    for (int o = 16; o > 0; o >>= 1) {
        s  += __shfl_xor_sync(0xffffffffu, s,  o);
        s2 += __shfl_xor_sync(0xffffffffu, s2, o);
    }
    if ((tid & 31) == 0) { rs[tid>>5] = s; rs2[tid>>5] = s2; }
    __syncthreads();
    s = rs[tid & 7]; s2 = rs2[tid & 7];
#pragma unroll
    for (int o = 4; o > 0; o >>= 1) {
        s  += __shfl_xor_sync(0xffffffffu, s,  o);
        s2 += __shfl_xor_sync(0xffffffffu, s2, o);
    }
    float mu  = s * (1.f/HD);
    float var = s2 * (1.f/HD) - mu*mu;
    float rstd = rsqrtf(var + 1e-5f);
#pragma unroll
    for (int i = 0; i < 3; i++) {
        int c = tid + 256*i;
        float x = (v[i] - mu) * rstd * g[c] + b[c];
        if (sel == 2) x = fmaxf(x, 0.f);
        base[c] = x;
    }
}

// ---------------- kernel 3: attention scores + row softmax --------------
// grid: 8 graphs * 6 heads * 3 row-blocks(32) = 144 blocks
__global__ __launch_bounds__(256) void k_scores() {
    int b = blockIdx.x;
    int rb = b % 3, head = (b/3) % HH, gph = b / (3*HH);
    __shared__ float Qs[32][129];
    __shared__ float Ks[48][129];
    __shared__ int mem[MM];
    int tid = threadIdx.x;
    if (tid < MM) mem[tid] = g_mem[gph*MM + tid];
    __syncthreads();
#pragma unroll
    for (int i = 0; i < 4; i++) {
        int lin = tid + i*256;
        int row = lin >> 5, c4 = lin & 31;
        int node = mem[rb*32 + row];
        float4 v = *(const float4*)&g_p[node*HD + head*DD + c4*4];
        Qs[row][c4*4+0]=v.x; Qs[row][c4*4+1]=v.y; Qs[row][c4*4+2]=v.z; Qs[row][c4*4+3]=v.w;
    }
    int tx = tid & 15, ty = tid >> 4;
    float S[2][6];
    for (int ch = 0; ch < 2; ch++) {
        __syncthreads();
#pragma unroll
        for (int i = 0; i < 6; i++) {
            int lin = tid + i*256;
            int row = lin >> 5, c4 = lin & 31;
            int node = mem[ch*48 + row];
            float4 v = *(const float4*)&g_p[PSZ + node*HD + head*DD + c4*4];
            Ks[row][c4*4+0]=v.x; Ks[row][c4*4+1]=v.y; Ks[row][c4*4+2]=v.z; Ks[row][c4*4+3]=v.w;
        }
        __syncthreads();
        float acc[2][3] = {};
#pragma unroll 4
        for (int d = 0; d < DD; d++) {
            float a0 = Qs[ty*2+0][d];
            float a1 = Qs[ty*2+1][d];
#pragma unroll
            for (int j = 0; j < 3; j++) {
                float bb = Ks[tx + 16*j][d];
                acc[0][j] += a0*bb;
                acc[1][j] += a1*bb;
            }
        }
#pragma unroll
        for (int i = 0; i < 2; i++)
#pragma unroll
            for (int j = 0; j < 3; j++) S[i][ch*3+j] = acc[i][j] * SCALE;
    }
    // per-row softmax: row lives in 16 consecutive lanes (tx), width-16 shuffles
#pragma unroll
    for (int i = 0; i < 2; i++) {
        float mx = S[i][0];
#pragma unroll
        for (int j = 1; j < 6; j++) mx = fmaxf(mx, S[i][j]);
#pragma unroll
        for (int o = 8; o > 0; o >>= 1) mx = fmaxf(mx, __shfl_xor_sync(0xffffffffu, mx, o));
        float sum = 0.f;
#pragma unroll
        for (int j = 0; j < 6; j++) { S[i][j] = __expf(S[i][j] - mx); sum += S[i][j]; }
#pragma unroll
        for (int o = 8; o > 0; o >>= 1) sum += __shfl_xor_sync(0xffffffffu, sum, o);
        float inv = 1.f / sum;
        int rglob = rb*32 + ty*2 + i;
        int base = ((gph*HH + head)*MM + rglob)*MM;
#pragma unroll
        for (int jj = 0; jj < 6; jj++) {
            int ch2 = jj / 3, j = jj % 3;
            g_s[base + ch2*48 + tx + 16*j] = S[i][jj] * inv;
        }
    }
}

// ---------------- kernel 4: out = S @ V ---------------------------------
__global__ __launch_bounds__(256) void k_av() {
    int b = blockIdx.x;
    int rb = b % 3, head = (b/3) % HH, gph = b / (3*HH);
    __shared__ float Ss[32][97];
    __shared__ float Vs[32][132];
    __shared__ int mem[MM];
    int tid = threadIdx.x;
    if (tid < MM) mem[tid] = g_mem[gph*MM + tid];
    __syncthreads();
#pragma unroll
    for (int i = 0; i < 3; i++) {
        int lin = tid + i*256;          // 768 float4s total
        int row = lin / 24, c4 = lin % 24;
        float4 v = *(const float4*)&g_s[((gph*HH+head)*MM + rb*32 + row)*MM + c4*4];
        Ss[row][c4*4+0]=v.x; Ss[row][c4*4+1]=v.y; Ss[row][c4*4+2]=v.z; Ss[row][c4*4+3]=v.w;
    }
    int tx = tid & 15, ty = tid >> 4;
    float acc[2][8] = {};
    for (int kc = 0; kc < 3; kc++) {
        __syncthreads();
#pragma unroll
        for (int i = 0; i < 4; i++) {
            int lin = tid + i*256;
            int row = lin >> 5, c4 = lin & 31;
            int node = mem[kc*32 + row];
            float4 v = *(const float4*)&g_p[2*PSZ + node*HD + head*DD + c4*4];
            *(float4*)&Vs[row][c4*4] = v;
        }
        __syncthreads();
#pragma unroll 4
        for (int kk = 0; kk < 32; kk++) {
            float a0 = Ss[ty*2+0][kc*32+kk];
            float a1 = Ss[ty*2+1][kc*32+kk];
#pragma unroll
            for (int j = 0; j < 8; j++) {
                float bb = Vs[kk][tx + 16*j];
                acc[0][j] += a0*bb;
                acc[1][j] += a1*bb;
            }
        }
    }
#pragma unroll
    for (int i = 0; i < 2; i++) {
        int node = mem[rb*32 + ty*2 + i];
#pragma unroll
        for (int j = 0; j < 8; j++)
            g_att[node*HD + head*DD + tx + 16*j] = acc[i][j];
    }
}

// ---------------- kernel 5: r1 = relu(ln(att @ Wo1^T))  K=768 -----------
__global__ __launch_bounds__(256) void k_o1(const float* __restrict__ Wo1,
                                            const float* __restrict__ go1,
                                            const float* __restrict__ bo1) {
    __shared__ float As[16][65];
    __shared__ float Bs[128][65];
    int m0 = blockIdx.x * 16;
    int tid = threadIdx.x, tx = tid & 15, ty = tid >> 4;
    float acc[8] = {};
    for (int kc = 0; kc < 12; kc++) {
        int k0 = kc * 64;
        {
            int row = tid >> 4, c4 = tid & 15;
            float4 v = *(const float4*)&g_att[(m0+row)*HD + k0 + c4*4];
            As[row][c4*4+0]=v.x; As[row][c4*4+1]=v.y; As[row][c4*4+2]=v.z; As[row][c4*4+3]=v.w;
        }
#pragma unroll
        for (int i = 0; i < 8; i++) {
            int lin = tid + i*256;
            int row = lin >> 4, c4 = lin & 15;
            float4 v = *(const float4*)&Wo1[row*HD + k0 + c4*4];
            Bs[row][c4*4+0]=v.x; Bs[row][c4*4+1]=v.y; Bs[row][c4*4+2]=v.z; Bs[row][c4*4+3]=v.w;
        }
        __syncthreads();
#pragma unroll 8
        for (int k = 0; k < 64; k++) {
            float a = As[ty][k];
#pragma unroll
            for (int j = 0; j < 8; j++) acc[j] += a * Bs[tx + 16*j][k];
        }
        __syncthreads();
    }
    float s = 0.f, s2 = 0.f;
#pragma unroll
    for (int j = 0; j < 8; j++) { s += acc[j]; s2 += acc[j]*acc[j]; }
#pragma unroll
    for (int o = 8; o > 0; o >>= 1) {
        s  += __shfl_xor_sync(0xffffffffu, s,  o);
        s2 += __shfl_xor_sync(0xffffffffu, s2, o);
    }
    float mu = s * (1.f/DD), var = s2 * (1.f/DD) - mu*mu;
    float rstd = rsqrtf(var + 1e-5f);
#pragma unroll
    for (int j = 0; j < 8; j++) {
        int c = tx + 16*j;
        float x = (acc[j] - mu) * rstd * go1[c] + bo1[c];
        g_r1[(m0+ty)*DD + c] = fmaxf(x, 0.f);
    }
}

// --------- kernel 6: h = relu(ln(nodes@W1^T + r1@Wo2^T))  K=256 ---------
__global__ __launch_bounds__(256) void k_mid(const float* __restrict__ W1,
                                             const float* __restrict__ Wo2,
                                             const float* __restrict__ gn,
                                             const float* __restrict__ bn) {
    __shared__ float As[16][65];
    __shared__ float Bs[128][65];
    int m0 = blockIdx.x * 16;
    int tid = threadIdx.x, tx = tid & 15, ty = tid >> 4;
    float acc[8] = {};
    for (int kc = 0; kc < 4; kc++) {
        int k0 = (kc & 1) * 64;
        const float* A = (kc < 2) ? g_nodes : g_r1;
        const float* W = (kc < 2) ? W1 : Wo2;
        {
            int row = tid >> 4, c4 = tid & 15;
            float4 v = *(const float4*)&A[(m0+row)*DD + k0 + c4*4];
            As[row][c4*4+0]=v.x; As[row][c4*4+1]=v.y; As[row][c4*4+2]=v.z; As[row][c4*4+3]=v.w;
        }
#pragma unroll
        for (int i = 0; i < 8; i++) {
            int lin = tid + i*256;
            int row = lin >> 4, c4 = lin & 15;
            float4 v = *(const float4*)&W[row*DD + k0 + c4*4];
            Bs[row][c4*4+0]=v.x; Bs[row][c4*4+1]=v.y; Bs[row][c4*4+2]=v.z; Bs[row][c4*4+3]=v.w;
        }
        __syncthreads();
#pragma unroll 8
        for (int k = 0; k < 64; k++) {
            float a = As[ty][k];
#pragma unroll
            for (int j = 0; j < 8; j++) acc[j] += a * Bs[tx + 16*j][k];
        }
        __syncthreads();
    }
    float s = 0.f, s2 = 0.f;
#pragma unroll
    for (int j = 0; j < 8; j++) { s += acc[j]; s2 += acc[j]*acc[j]; }
#pragma unroll
    for (int o = 8; o > 0; o >>= 1) {
        s  += __shfl_xor_sync(0xffffffffu, s,  o);
        s2 += __shfl_xor_sync(0xffffffffu, s2, o);
    }
    float mu = s * (1.f/DD), var = s2 * (1.f/DD) - mu*mu;
    float rstd = rsqrtf(var + 1e-5f);
#pragma unroll
    for (int j = 0; j < 8; j++) {
        int c = tx + 16*j;
        float x = (acc[j] - mu) * rstd * gn[c] + bn[c];
        g_h[(m0+ty)*DD + c] = fmaxf(x, 0.f);
    }
}

// ---- kernel 7: out = relu(h@W2^T + nodes), scattered to output order ---
__global__ __launch_bounds__(256) void k_final(const float* __restrict__ W2,
                                               float* __restrict__ out) {
    __shared__ float As[16][65];
    __shared__ float Bs[128][65];
    int m0 = blockIdx.x * 16;
    int tid = threadIdx.x, tx = tid & 15, ty = tid >> 4;
    float acc[8] = {};
    for (int kc = 0; kc < 2; kc++) {
        int k0 = kc * 64;
        {
            int row = tid >> 4, c4 = tid & 15;
            float4 v = *(const float4*)&g_h[(m0+row)*DD + k0 + c4*4];
            As[row][c4*4+0]=v.x; As[row][c4*4+1]=v.y; As[row][c4*4+2]=v.z; As[row][c4*4+3]=v.w;
        }
#pragma unroll
        for (int i = 0; i < 8; i++) {
            int lin = tid + i*256;
            int row = lin >> 4, c4 = lin & 15;
            float4 v = *(const float4*)&W2[row*DD + k0 + c4*4];
            Bs[row][c4*4+0]=v.x; Bs[row][c4*4+1]=v.y; Bs[row][c4*4+2]=v.z; Bs[row][c4*4+3]=v.w;
        }
        __syncthreads();
#pragma unroll 8
        for (int k = 0; k < 64; k++) {
            float a = As[ty][k];
#pragma unroll
            for (int j = 0; j < 8; j++) acc[j] += a * Bs[tx + 16*j][k];
        }
        __syncthreads();
    }
    int row = m0 + ty;
    int orow = g_inv[row];
#pragma unroll
    for (int j = 0; j < 8; j++) {
        int c = tx + 16*j;
        float x = acc[j] + g_nodes[row*DD + c];
        out[orow*DD + c] = fmaxf(x, 0.f);
    }
}

// ------------------------------------------------------------------------
extern "C" void kernel_launch(void* const* d_in, const int* in_sizes, int n_in,
                              void* d_out, int out_size) {
    const float* agents    = (const float*)d_in[0];
    const int*   agent_ids = (const int*)  d_in[1];
    const float* lanes     = (const float*)d_in[2];
    const int*   lane_ids  = (const int*)  d_in[3];
    const float* Wq  = (const float*)d_in[4];
    const float* gq  = (const float*)d_in[5];
    const float* bq  = (const float*)d_in[6];
    const float* Wk  = (const float*)d_in[7];
    const float* gk  = (const float*)d_in[8];
    const float* bk  = (const float*)d_in[9];
    const float* Wv  = (const float*)d_in[10];
    const float* gv  = (const float*)d_in[11];
    const float* bv  = (const float*)d_in[12];
    const float* Wo1 = (const float*)d_in[13];
    const float* go1 = (const float*)d_in[14];
    const float* bo1 = (const float*)d_in[15];
    const float* Wo2 = (const float*)d_in[16];
    const float* W1  = (const float*)d_in[17];
    const float* gn  = (const float*)d_in[18];
    const float* bn  = (const float*)d_in[19];
    const float* W2  = (const float*)d_in[20];
    float* out = (float*)d_out;

    k_prep  <<<(NN*DD + 255)/256, 256>>>(agents, agent_ids, lanes, lane_ids);
    k_qkv   <<<dim3(12, 36), 256>>>(Wq, Wk, Wv);
    k_ln    <<<dim3(NN, 3), 256>>>(gq, bq, gk, bk, gv, bv);
    k_scores<<<NG*HH*3, 256>>>();
    k_av    <<<NG*HH*3, 256>>>();
    k_o1    <<<NN/16, 256>>>(Wo1, go1, bo1);
    k_mid   <<<NN/16, 256>>>(W1, Wo2, gn, bn);
    k_final <<<NN/16, 256>>>(W2, out);
}

// round 2
// speedup vs baseline: 1.5263x; 1.5263x over previous
#include <cuda_runtime.h>

#define NN 768
#define NA 192
#define NL 576
#define DD 128
#define HH 6
#define HD 768
#define NG 8
#define MM 96
#define PSZ (HD*NN)

#define SCALE 0.08838834764831845f

// ---------------- device scratch ----------------
__device__ float g_p[3*PSZ];          // q,k,v projections (LN'd in place)
__device__ float g_att[NN*HD];        // attention output
__device__ float g_part[4*NN*DD];     // o1 split-K partials
__device__ int   g_inv[NN];           // node -> output row

// ============ kernel 1: QKV GEMM  P = nodes @ W^T  (768 x 2304, K=128) ====
// BM=64, BN=128, BK=32, microtile 4x8, 256 threads. Block (0,0) also builds g_inv.
__global__ __launch_bounds__(256) void k_qkv(const float* __restrict__ agents,
                                             const float* __restrict__ lanes,
                                             const int* __restrict__ agent_ids,
                                             const int* __restrict__ lane_ids,
                                             const float* __restrict__ Wq,
                                             const float* __restrict__ Wk,
                                             const float* __restrict__ Wv) {
    __shared__ float As[64*33];
    __shared__ float Bs[128*33];
    int tid = threadIdx.x;
    if (blockIdx.x == 0 && blockIdx.y == 0) {
        for (int t = tid; t < NN; t += 256) {
            if (t < NA) g_inv[t < NA ? agent_ids[t] : 0] = t;
            else        g_inv[NA + lane_ids[t - NA]] = t;
        }
    }
    int m0  = blockIdx.x * 64;
    int sel = blockIdx.y / 6;
    int w0  = (blockIdx.y % 6) * 128;
    const float* W = sel == 0 ? Wq : (sel == 1 ? Wk : Wv);
    const float* Ab = m0 < NA ? agents + m0*DD : lanes + (m0 - NA)*DD;
    int tx = tid & 15, ty = tid >> 4;
    float acc[4][8] = {};
    for (int kc = 0; kc < 4; kc++) {
        int k0 = kc * 32;
#pragma unroll
        for (int i = 0; i < 2; i++) {              // A: 64x32 = 512 f4
            int lin = tid + i*256;
            int row = lin >> 3, c4 = lin & 7;
            float4 v = *(const float4*)&Ab[row*DD + k0 + c4*4];
            float* d = &As[row*33 + c4*4];
            d[0]=v.x; d[1]=v.y; d[2]=v.z; d[3]=v.w;
        }
#pragma unroll
        for (int i = 0; i < 4; i++) {              // B: 128x32 = 1024 f4
            int lin = tid + i*256;
            int row = lin >> 3, c4 = lin & 7;
            float4 v = *(const float4*)&W[(w0+row)*DD + k0 + c4*4];
            float* d = &Bs[row*33 + c4*4];
            d[0]=v.x; d[1]=v.y; d[2]=v.z; d[3]=v.w;
        }
        __syncthreads();
#pragma unroll 4
        for (int k = 0; k < 32; k++) {
            float a[4], b[8];
#pragma unroll
            for (int i = 0; i < 4; i++) a[i] = As[(ty + 16*i)*33 + k];
#pragma unroll
            for (int j = 0; j < 8; j++) b[j] = Bs[(tx + 16*j)*33 + k];
#pragma unroll
            for (int i = 0; i < 4; i++)
#pragma unroll
                for (int j = 0; j < 8; j++) acc[i][j] += a[i]*b[j];
        }
        __syncthreads();
    }
    float* out = g_p + sel*PSZ;
#pragma unroll
    for (int i = 0; i < 4; i++)
#pragma unroll
        for (int j = 0; j < 8; j++)
            out[(m0 + ty + 16*i)*HD + w0 + tx + 16*j] = acc[i][j];
}

// ============ kernel 2: LayerNorm over HD=768 (in place; ReLU for V) ======
__global__ __launch_bounds__(256) void k_ln(const float* __restrict__ gq, const float* __restrict__ bq,
                                            const float* __restrict__ gk, const float* __restrict__ bk,
                                            const float* __restrict__ gv, const float* __restrict__ bv) {
    int row = blockIdx.x, sel = blockIdx.y;
    float* base = g_p + sel*PSZ + row*HD;
    const float* g = sel==0 ? gq : (sel==1 ? gk : gv);
    const float* b = sel==0 ? bq : (sel==1 ? bk : bv);
    int tid = threadIdx.x;
    float v[3]; float s = 0.f, s2 = 0.f;
#pragma unroll
    for (int i = 0; i < 3; i++) {
        v[i] = base[tid + 256*i];
        s += v[i]; s2 += v[i]*v[i];
    }
    __shared__ float rs[8], rs2[8];
#pragma unroll
    for (int o = 16; o > 0; o >>= 1) {
        s  += __shfl_xor_sync(0xffffffffu, s,  o);
        s2 += __shfl_xor_sync(0xffffffffu, s2, o);
    }
    if ((tid & 31) == 0) { rs[tid>>5] = s; rs2[tid>>5] = s2; }
    __syncthreads();
    s = rs[tid & 7]; s2 = rs2[tid & 7];
#pragma unroll
    for (int o = 4; o > 0; o >>= 1) {
        s  += __shfl_xor_sync(0xffffffffu, s,  o);
        s2 += __shfl_xor_sync(0xffffffffu, s2, o);
    }
    float mu  = s * (1.f/HD);
    float var = s2 * (1.f/HD) - mu*mu;
    float rstd = rsqrtf(var + 1e-5f);
#pragma unroll
    for (int i = 0; i < 3; i++) {
        int c = tid + 256*i;
        float x = (v[i] - mu) * rstd * g[c] + b[c];
        if (sel == 2) x = fmaxf(x, 0.f);
        base[c] = x;
    }
}

// ============ kernel 3: fused attention per (graph, head, 32-row block) ===
// dyn smem: Qs[32][128] (reused as Ss[32][97]) + KV[96][129] + mem[96]
#define ATTN_SMEM ((32*128 + 96*129)*4 + 96*4)
__global__ __launch_bounds__(256) void k_attn(const int* __restrict__ agent_ids,
                                              const int* __restrict__ lane_ids) {
    extern __shared__ float sm[];
    float* Qs = sm;                     // pitch 128 (broadcast reads)
    float* Ss = sm;                     // pitch 97, aliases Qs
    float* KV = sm + 32*128;            // pitch 129
    int* mem  = (int*)(sm + 32*128 + 96*129);

    int b = blockIdx.x;
    int rb = b % 3, head = (b/3) % HH, gph = b / (3*HH);
    int tid = threadIdx.x;
    if (tid < MM) {
        mem[tid] = tid < 24 ? agent_ids[gph*24 + tid]
                            : NA + lane_ids[gph*72 + (tid - 24)];
    }
    __syncthreads();
    // load Q (32 rows) and K (96 rows)
#pragma unroll
    for (int i = 0; i < 4; i++) {
        int lin = tid + i*256;
        int row = lin >> 5, c4 = lin & 31;
        int node = mem[rb*32 + row];
        float4 v = *(const float4*)&g_p[node*HD + head*DD + c4*4];
        float* d = &Qs[row*128 + c4*4];
        d[0]=v.x; d[1]=v.y; d[2]=v.z; d[3]=v.w;
    }
#pragma unroll
    for (int i = 0; i < 12; i++) {
        int lin = tid + i*256;
        int row = lin >> 5, c4 = lin & 31;
        int node = mem[row];
        float4 v = *(const float4*)&g_p[PSZ + node*HD + head*DD + c4*4];
        float* d = &KV[row*129 + c4*4];
        d[0]=v.x; d[1]=v.y; d[2]=v.z; d[3]=v.w;
    }
    __syncthreads();

    int tx = tid & 15, ty = tid >> 4;     // rows 2ty,2ty+1; cols tx+16j (j<6)
    float S[2][6] = {};
#pragma unroll 4
    for (int d = 0; d < DD; d++) {
        float a0 = Qs[(2*ty+0)*128 + d];
        float a1 = Qs[(2*ty+1)*128 + d];
#pragma unroll
        for (int j = 0; j < 6; j++) {
            float bb = KV[(tx + 16*j)*129 + d];
            S[0][j] += a0*bb;
            S[1][j] += a1*bb;
        }
    }
    // softmax per row (row spans 16 lanes)
    float p[2][6]; float inv[2];
#pragma unroll
    for (int i = 0; i < 2; i++) {
        float mx = S[i][0] * SCALE;
#pragma unroll
        for (int j = 1; j < 6; j++) mx = fmaxf(mx, S[i][j]*SCALE);
#pragma unroll
        for (int o = 8; o > 0; o >>= 1) mx = fmaxf(mx, __shfl_xor_sync(0xffffffffu, mx, o));
        float sum = 0.f;
#pragma unroll
        for (int j = 0; j < 6; j++) { p[i][j] = __expf(S[i][j]*SCALE - mx); sum += p[i][j]; }
#pragma unroll
        for (int o = 8; o > 0; o >>= 1) sum += __shfl_xor_sync(0xffffffffu, sum, o);
        inv[i] = 1.f / sum;
    }
    __syncthreads();   // all K reads + Q reads done
    // write S into (former Q) buffer; load V into KV buffer
#pragma unroll
    for (int i = 0; i < 2; i++)
#pragma unroll
        for (int j = 0; j < 6; j++)
            Ss[(2*ty+i)*97 + tx + 16*j] = p[i][j] * inv[i];
#pragma unroll
    for (int i = 0; i < 12; i++) {
        int lin = tid + i*256;
        int row = lin >> 5, c4 = lin & 31;
        int node = mem[row];
        float4 v = *(const float4*)&g_p[2*PSZ + node*HD + head*DD + c4*4];
        float* d = &KV[row*129 + c4*4];
        d[0]=v.x; d[1]=v.y; d[2]=v.z; d[3]=v.w;
    }
    __syncthreads();
    // out = S @ V : rows 2ty+i, cols tx+16j (j<8)
    float acc[2][8] = {};
#pragma unroll 4
    for (int kk = 0; kk < MM; kk++) {
        float s0 = Ss[(2*ty+0)*97 + kk];
        float s1 = Ss[(2*ty+1)*97 + kk];
#pragma unroll
        for (int j = 0; j < 8; j++) {
            float vv = KV[kk*129 + tx + 16*j];
            acc[0][j] += s0*vv;
            acc[1][j] += s1*vv;
        }
    }
#pragma unroll
    for (int i = 0; i < 2; i++) {
        int node = mem[rb*32 + 2*ty + i];
#pragma unroll
        for (int j = 0; j < 8; j++)
            g_att[node*HD + head*DD + tx + 16*j] = acc[i][j];
    }
}

// ============ kernel 4: o1 split-K  partial = att @ Wo1^T (K-split 192) ===
// grid (48, 4): 16-row tiles x 4 K-splits, microtile 2x4, 256 threads
__global__ __launch_bounds__(256) void k_o1s(const float* __restrict__ Wo1) {
    __shared__ float As[16*64];
    __shared__ float Bs[128*65];
    int m0 = blockIdx.x * 16;
    int sp = blockIdx.y;
    int kbase = sp * 192;
    int tid = threadIdx.x, tx = tid & 31, ty = tid >> 5;
    float acc[2][4] = {};
    for (int cc = 0; cc < 3; cc++) {
        int k0 = kbase + cc*64;
        {
            int row = tid >> 4, c4 = tid & 15;   // 16x16 f4
            float4 v = *(const float4*)&g_att[(m0+row)*HD + k0 + c4*4];
            float* d = &As[row*64 + c4*4];
            d[0]=v.x; d[1]=v.y; d[2]=v.z; d[3]=v.w;
        }
#pragma unroll
        for (int i = 0; i < 8; i++) {
            int lin = tid + i*256;
            int row = lin >> 4, c4 = lin & 15;
            float4 v = *(const float4*)&Wo1[row*HD + k0 + c4*4];
            float* d = &Bs[row*65 + c4*4];
            d[0]=v.x; d[1]=v.y; d[2]=v.z; d[3]=v.w;
        }
        __syncthreads();
#pragma unroll 4
        for (int k = 0; k < 64; k++) {
            float a0 = As[(2*ty+0)*64 + k];
            float a1 = As[(2*ty+1)*64 + k];
#pragma unroll
            for (int j = 0; j < 4; j++) {
                float bb = Bs[(tx + 32*j)*65 + k];
                acc[0][j] += a0*bb;
                acc[1][j] += a1*bb;
            }
        }
        __syncthreads();
    }
#pragma unroll
    for (int i = 0; i < 2; i++)
#pragma unroll
        for (int j = 0; j < 4; j++)
            g_part[sp*(NN*DD) + (m0 + 2*ty + i)*DD + tx + 32*j] = acc[i][j];
}

// ============ kernel 5: tail = reduce+LN+relu -> mid GEMM+LN+relu ->
//                               final GEMM + residual + relu + scatter ====
__global__ __launch_bounds__(256) void k_tail(const float* __restrict__ agents,
                                              const float* __restrict__ lanes,
                                              const float* __restrict__ go1,
                                              const float* __restrict__ bo1,
                                              const float* __restrict__ W1,
                                              const float* __restrict__ Wo2,
                                              const float* __restrict__ gn,
                                              const float* __restrict__ bn,
                                              const float* __restrict__ W2,
                                              float* __restrict__ out) {
    __shared__ float nodes_s[16*128];
    __shared__ float buf[16*128];
    __shared__ float Bs[128*33];
    int m0 = blockIdx.x * 16;
    int tid = threadIdx.x, tx = tid & 31, ty = tid >> 5;
    const float* Ab = m0 < NA ? agents + m0*DD : lanes + (m0 - NA)*DD;
#pragma unroll
    for (int i = 0; i < 2; i++) {                 // nodes: 16x32 f4
        int lin = tid + i*256;
        int row = lin >> 5, c4 = lin & 31;
        float4 v = *(const float4*)&Ab[row*DD + c4*4];
        float* d = &nodes_s[row*128 + c4*4];
        d[0]=v.x; d[1]=v.y; d[2]=v.z; d[3]=v.w;
    }
    // sum o1 partials
#pragma unroll
    for (int i = 0; i < 8; i++) {
        int e = tid + i*256;
        float s = 0.f;
#pragma unroll
        for (int sp = 0; sp < 4; sp++) s += g_part[sp*(NN*DD) + m0*DD + e];
        buf[e] = s;
    }
    __syncthreads();
    // LN + relu over rows of buf (warp w handles rows 2w,2w+1)
    {
        int w = tid >> 5, lane = tid & 31;
#pragma unroll
        for (int i = 0; i < 2; i++) {
            int r = 2*w + i;
            float x[4]; float s = 0.f, s2 = 0.f;
#pragma unroll
            for (int e = 0; e < 4; e++) {
                x[e] = buf[r*128 + lane + 32*e];
                s += x[e]; s2 += x[e]*x[e];
            }
#pragma unroll
            for (int o = 16; o > 0; o >>= 1) {
                s  += __shfl_xor_sync(0xffffffffu, s,  o);
                s2 += __shfl_xor_sync(0xffffffffu, s2, o);
            }
            float mu = s*(1.f/DD), var = s2*(1.f/DD) - mu*mu;
            float rstd = rsqrtf(var + 1e-5f);
#pragma unroll
            for (int e = 0; e < 4; e++) {
                int c = lane + 32*e;
                buf[r*128 + c] = fmaxf((x[e]-mu)*rstd*go1[c] + bo1[c], 0.f);
            }
        }
    }
    __syncthreads();
    // mid GEMM: nodes@W1^T + r1@Wo2^T
    float acc[2][4] = {};
    for (int cc = 0; cc < 8; cc++) {
        const float* W = cc < 4 ? W1 : Wo2;
        const float* A = cc < 4 ? nodes_s : buf;
        int k0 = (cc & 3) * 32;
#pragma unroll
        for (int i = 0; i < 4; i++) {              // 128x8 f4
            int lin = tid + i*256;
            int row = lin >> 3, c4 = lin & 7;
            float4 v = *(const float4*)&W[row*DD + k0 + c4*4];
            float* d = &Bs[row*33 + c4*4];
            d[0]=v.x; d[1]=v.y; d[2]=v.z; d[3]=v.w;
        }
        __syncthreads();
#pragma unroll 4
        for (int k = 0; k < 32; k++) {
            float a0 = A[(2*ty+0)*128 + k0 + k];
            float a1 = A[(2*ty+1)*128 + k0 + k];
#pragma unroll
            for (int j = 0; j < 4; j++) {
                float bb = Bs[(tx + 32*j)*33 + k];
                acc[0][j] += a0*bb;
                acc[1][j] += a1*bb;
            }
        }
        __syncthreads();
    }
#pragma unroll
    for (int i = 0; i < 2; i++)
#pragma unroll
        for (int j = 0; j < 4; j++)
            buf[(2*ty+i)*128 + tx + 32*j] = acc[i][j];
    __syncthreads();
    // LN + relu -> h (in buf)
    {
        int w = tid >> 5, lane = tid & 31;
#pragma unroll
        for (int i = 0; i < 2; i++) {
            int r = 2*w + i;
            float x[4]; float s = 0.f, s2 = 0.f;
#pragma unroll
            for (int e = 0; e < 4; e++) {
                x[e] = buf[r*128 + lane + 32*e];
                s += x[e]; s2 += x[e]*x[e];
            }
#pragma unroll
            for (int o = 16; o > 0; o >>= 1) {
                s  += __shfl_xor_sync(0xffffffffu, s,  o);
                s2 += __shfl_xor_sync(0xffffffffu, s2, o);
            }
            float mu = s*(1.f/DD), var = s2*(1.f/DD) - mu*mu;
            float rstd = rsqrtf(var + 1e-5f);
#pragma unroll
            for (int e = 0; e < 4; e++) {
                int c = lane + 32*e;
                buf[r*128 + c] = fmaxf((x[e]-mu)*rstd*gn[c] + bn[c], 0.f);
            }
        }
    }
    __syncthreads();
    // final GEMM: h @ W2^T
    float acc2[2][4] = {};
    for (int cc = 0; cc < 4; cc++) {
        int k0 = cc * 32;
#pragma unroll
        for (int i = 0; i < 4; i++) {
            int lin = tid + i*256;
            int row = lin >> 3, c4 = lin & 7;
            float4 v = *(const float4*)&W2[row*DD + k0 + c4*4];
            float* d = &Bs[row*33 + c4*4];
            d[0]=v.x; d[1]=v.y; d[2]=v.z; d[3]=v.w;
        }
        __syncthreads();
#pragma unroll 4
        for (int k = 0; k < 32; k++) {
            float a0 = buf[(2*ty+0)*128 + k0 + k];
            float a1 = buf[(2*ty+1)*128 + k0 + k];
#pragma unroll
            for (int j = 0; j < 4; j++) {
                float bb = Bs[(tx + 32*j)*33 + k];
                acc2[0][j] += a0*bb;
                acc2[1][j] += a1*bb;
            }
        }
        __syncthreads();
    }
#pragma unroll
    for (int i = 0; i < 2; i++) {
        int r = 2*ty + i;
        int orow = g_inv[m0 + r];
#pragma unroll
        for (int j = 0; j < 4; j++) {
            int c = tx + 32*j;
            float x = acc2[i][j] + nodes_s[r*128 + c];
            out[orow*DD + c] = fmaxf(x, 0.f);
        }
    }
}

// ------------------------------------------------------------------------
extern "C" void kernel_launch(void* const* d_in, const int* in_sizes, int n_in,
                              void* d_out, int out_size) {
    const float* agents    = (const float*)d_in[0];
    const int*   agent_ids = (const int*)  d_in[1];
    const float* lanes     = (const float*)d_in[2];
    const int*   lane_ids  = (const int*)  d_in[3];
    const float* Wq  = (const float*)d_in[4];
    const float* gq  = (const float*)d_in[5];
    const float* bq  = (const float*)d_in[6];
    const float* Wk  = (const float*)d_in[7];
    const float* gk  = (const float*)d_in[8];
    const float* bk  = (const float*)d_in[9];
    const float* Wv  = (const float*)d_in[10];
    const float* gv  = (const float*)d_in[11];
    const float* bv  = (const float*)d_in[12];
    const float* Wo1 = (const float*)d_in[13];
    const float* go1 = (const float*)d_in[14];
    const float* bo1 = (const float*)d_in[15];
    const float* Wo2 = (const float*)d_in[16];
    const float* W1  = (const float*)d_in[17];
    const float* gn  = (const float*)d_in[18];
    const float* bn  = (const float*)d_in[19];
    const float* W2  = (const float*)d_in[20];
    float* out = (float*)d_out;

    cudaFuncSetAttribute(k_attn, cudaFuncAttributeMaxDynamicSharedMemorySize, ATTN_SMEM);

    k_qkv <<<dim3(12, 18), 256>>>(agents, lanes, agent_ids, lane_ids, Wq, Wk, Wv);
    k_ln  <<<dim3(NN, 3), 256>>>(gq, bq, gk, bk, gv, bv);
    k_attn<<<NG*HH*3, 256, ATTN_SMEM>>>(agent_ids, lane_ids);
    k_o1s <<<dim3(48, 4), 256>>>(Wo1);
    k_tail<<<48, 256>>>(agents, lanes, go1, bo1, W1, Wo2, gn, bn, W2, out);
}

// round 3
// speedup vs baseline: 1.6090x; 1.0542x over previous
#include <cuda_runtime.h>

#define NN 768
#define NA 192
#define DD 128
#define HH 6
#define HD 768
#define NG 8
#define MM 96
#define PSZ (HD*NN)
#define SCALE 0.08838834764831845f
#define NSPLIT 8

// ---------------- device scratch ----------------
__device__ float g_p[3*PSZ];          // raw q,k,v projections (pre-LN)
__device__ float g_psum[3*NN*12];     // per (mat,row): 6 chunks x (sum, sumsq)
__device__ float g_att[NN*HD];        // attention output
__device__ float g_part[NSPLIT*NN*DD];// o1 split-K partials
__device__ int   g_inv[NN];           // node -> output row

// ============ kernel 1: QKV GEMM + row-stat partials =====================
// BM=64, BN=128, BK=32, microtile 4x8, 256 threads, float2-k inner loop.
__global__ __launch_bounds__(256) void k_qkv(const float* __restrict__ agents,
                                             const float* __restrict__ lanes,
                                             const int* __restrict__ agent_ids,
                                             const int* __restrict__ lane_ids,
                                             const float* __restrict__ Wq,
                                             const float* __restrict__ Wk,
                                             const float* __restrict__ Wv) {
    __shared__ float As[64*34];
    __shared__ float Bs[128*34];
    int tid = threadIdx.x;
    if (blockIdx.x == 0 && blockIdx.y == 0) {
        for (int t = tid; t < NN; t += 256) {
            if (t < NA) g_inv[agent_ids[t]] = t;
            else        g_inv[NA + lane_ids[t - NA]] = t;
        }
    }
    int m0  = blockIdx.x * 64;
    int sel = blockIdx.y / 6;
    int nch = blockIdx.y % 6;
    int w0  = nch * 128;
    const float* W = sel == 0 ? Wq : (sel == 1 ? Wk : Wv);
    const float* Ab = m0 < NA ? agents + m0*DD : lanes + (m0 - NA)*DD;
    int tx = tid & 15, ty = tid >> 4;
    float acc[4][8] = {};
    for (int kc = 0; kc < 4; kc++) {
        int k0 = kc * 32;
#pragma unroll
        for (int i = 0; i < 2; i++) {
            int lin = tid + i*256;
            int row = lin >> 3, c4 = lin & 7;
            float4 v = *(const float4*)&Ab[row*DD + k0 + c4*4];
            float* d = &As[row*34 + c4*4];
            d[0]=v.x; d[1]=v.y; d[2]=v.z; d[3]=v.w;
        }
#pragma unroll
        for (int i = 0; i < 4; i++) {
            int lin = tid + i*256;
            int row = lin >> 3, c4 = lin & 7;
            float4 v = *(const float4*)&W[(w0+row)*DD + k0 + c4*4];
            float* d = &Bs[row*34 + c4*4];
            d[0]=v.x; d[1]=v.y; d[2]=v.z; d[3]=v.w;
        }
        __syncthreads();
#pragma unroll 8
        for (int k = 0; k < 32; k += 2) {
            float2 a[4], b[8];
#pragma unroll
            for (int i = 0; i < 4; i++) a[i] = *(float2*)&As[(ty + 16*i)*34 + k];
#pragma unroll
            for (int j = 0; j < 8; j++) b[j] = *(float2*)&Bs[(tx + 16*j)*34 + k];
#pragma unroll
            for (int i = 0; i < 4; i++)
#pragma unroll
                for (int j = 0; j < 8; j++) {
                    acc[i][j] += a[i].x * b[j].x;
                    acc[i][j] += a[i].y * b[j].y;
                }
        }
        __syncthreads();
    }
    float* out = g_p + sel*PSZ;
#pragma unroll
    for (int i = 0; i < 4; i++)
#pragma unroll
        for (int j = 0; j < 8; j++)
            out[(m0 + ty + 16*i)*HD + w0 + tx + 16*j] = acc[i][j];
    // per-row partial stats (row lives on 16 consecutive lanes)
#pragma unroll
    for (int i = 0; i < 4; i++) {
        float s = 0.f, s2 = 0.f;
#pragma unroll
        for (int j = 0; j < 8; j++) { s += acc[i][j]; s2 += acc[i][j]*acc[i][j]; }
#pragma unroll
        for (int o = 8; o > 0; o >>= 1) {
            s  += __shfl_xor_sync(0xffffffffu, s,  o);
            s2 += __shfl_xor_sync(0xffffffffu, s2, o);
        }
        if (tx == 0) {
            int r = m0 + ty + 16*i;
            g_psum[(sel*NN + r)*12 + nch*2 + 0] = s;
            g_psum[(sel*NN + r)*12 + nch*2 + 1] = s2;
        }
    }
}

// ============ kernel 2: fused attention with inline LN ===================
#define KPITCH 130
#define VPITCH 98
#define SPITCH 98
// dyn smem floats: Qs 4096 | KV 12544 | s_mu 224 | s_rs 224 | s_g 384 | s_b 384 | mem 96i
#define ATTN_SMEM ((4096 + 12544 + 224 + 224 + 384 + 384)*4 + 96*4)
__global__ __launch_bounds__(256) void k_attn(const int* __restrict__ agent_ids,
                                              const int* __restrict__ lane_ids,
                                              const float* __restrict__ gq, const float* __restrict__ bq,
                                              const float* __restrict__ gk, const float* __restrict__ bk,
                                              const float* __restrict__ gv, const float* __restrict__ bv) {
    extern __shared__ float sm[];
    float* Qs  = sm;                    // pitch 128; aliased as Ss pitch 98
    float* Ss  = sm;
    float* KV  = sm + 4096;             // K: [96][130], then Vt: [128][98]
    float* s_mu = sm + 4096 + 12544;
    float* s_rs = s_mu + 224;
    float* s_g  = s_rs + 224;           // [mat*128 + c]
    float* s_b  = s_g + 384;
    int*   mem  = (int*)(s_b + 384);

    int b = blockIdx.x;
    int rb = b % 3, head = (b/3) % HH, gph = b / (3*HH);
    int tid = threadIdx.x;
    if (tid < MM)
        mem[tid] = tid < 24 ? agent_ids[gph*24 + tid]
                            : NA + lane_ids[gph*72 + (tid - 24)];
    __syncthreads();
    if (tid < 224) {
        int mat, node;
        if (tid < 32)       { mat = 0; node = mem[rb*32 + tid]; }
        else if (tid < 128) { mat = 1; node = mem[tid - 32]; }
        else                { mat = 2; node = mem[tid - 128]; }
        const float* ps = &g_psum[(mat*NN + node)*12];
        float s = 0.f, s2 = 0.f;
#pragma unroll
        for (int n = 0; n < 6; n++) { s += ps[2*n]; s2 += ps[2*n+1]; }
        float mu = s * (1.f/HD);
        float var = s2 * (1.f/HD) - mu*mu;
        s_mu[tid] = mu;
        s_rs[tid] = rsqrtf(var + 1e-5f);
    }
    for (int t = tid; t < 384; t += 256) {
        int mat = t >> 7, c = t & 127;
        const float* g = mat==0 ? gq : (mat==1 ? gk : gv);
        const float* bb = mat==0 ? bq : (mat==1 ? bk : bv);
        s_g[t] = g[head*DD + c];
        s_b[t] = bb[head*DD + c];
    }
    __syncthreads();
    // Q (32 rows) with LN affine
#pragma unroll
    for (int i = 0; i < 4; i++) {
        int lin = tid + i*256;
        int row = lin >> 5, c4 = lin & 31;
        int node = mem[rb*32 + row];
        float4 v = *(const float4*)&g_p[node*HD + head*DD + c4*4];
        float mu = s_mu[row], rs = s_rs[row];
        float* d = &Qs[row*128 + c4*4];
        d[0] = (v.x-mu)*rs*s_g[c4*4+0] + s_b[c4*4+0];
        d[1] = (v.y-mu)*rs*s_g[c4*4+1] + s_b[c4*4+1];
        d[2] = (v.z-mu)*rs*s_g[c4*4+2] + s_b[c4*4+2];
        d[3] = (v.w-mu)*rs*s_g[c4*4+3] + s_b[c4*4+3];
    }
    // K (96 rows) with LN affine
#pragma unroll
    for (int i = 0; i < 12; i++) {
        int lin = tid + i*256;
        int row = lin >> 5, c4 = lin & 31;
        int node = mem[row];
        float4 v = *(const float4*)&g_p[PSZ + node*HD + head*DD + c4*4];
        float mu = s_mu[32+row], rs = s_rs[32+row];
        float* d = &KV[row*KPITCH + c4*4];
        d[0] = (v.x-mu)*rs*s_g[128+c4*4+0] + s_b[128+c4*4+0];
        d[1] = (v.y-mu)*rs*s_g[128+c4*4+1] + s_b[128+c4*4+1];
        d[2] = (v.z-mu)*rs*s_g[128+c4*4+2] + s_b[128+c4*4+2];
        d[3] = (v.w-mu)*rs*s_g[128+c4*4+3] + s_b[128+c4*4+3];
    }
    __syncthreads();

    int tx = tid & 15, ty = tid >> 4;
    float S[2][6] = {};
#pragma unroll 4
    for (int d2 = 0; d2 < DD; d2 += 2) {
        float2 a0 = *(float2*)&Qs[(2*ty+0)*128 + d2];
        float2 a1 = *(float2*)&Qs[(2*ty+1)*128 + d2];
#pragma unroll
        for (int j = 0; j < 6; j++) {
            float2 kk = *(float2*)&KV[(tx + 16*j)*KPITCH + d2];
            S[0][j] += a0.x*kk.x; S[0][j] += a0.y*kk.y;
            S[1][j] += a1.x*kk.x; S[1][j] += a1.y*kk.y;
        }
    }
    float p[2][6]; float inv[2];
#pragma unroll
    for (int i = 0; i < 2; i++) {
        float mx = S[i][0] * SCALE;
#pragma unroll
        for (int j = 1; j < 6; j++) mx = fmaxf(mx, S[i][j]*SCALE);
#pragma unroll
        for (int o = 8; o > 0; o >>= 1) mx = fmaxf(mx, __shfl_xor_sync(0xffffffffu, mx, o));
        float sum = 0.f;
#pragma unroll
        for (int j = 0; j < 6; j++) { p[i][j] = __expf(S[i][j]*SCALE - mx); sum += p[i][j]; }
#pragma unroll
        for (int o = 8; o > 0; o >>= 1) sum += __shfl_xor_sync(0xffffffffu, sum, o);
        inv[i] = 1.f / sum;
    }
    __syncthreads();
    // S -> smem (aliases Q); V loaded TRANSPOSED (Vt[col][kk]) with LN+relu
#pragma unroll
    for (int i = 0; i < 2; i++)
#pragma unroll
        for (int j = 0; j < 6; j++)
            Ss[(2*ty+i)*SPITCH + tx + 16*j] = p[i][j] * inv[i];
#pragma unroll
    for (int i = 0; i < 12; i++) {
        int lin = tid + i*256;
        int row = lin >> 5, c4 = lin & 31;
        int node = mem[row];
        float4 v = *(const float4*)&g_p[2*PSZ + node*HD + head*DD + c4*4];
        float mu = s_mu[128+row], rs = s_rs[128+row];
        KV[(c4*4+0)*VPITCH + row] = fmaxf((v.x-mu)*rs*s_g[256+c4*4+0] + s_b[256+c4*4+0], 0.f);
        KV[(c4*4+1)*VPITCH + row] = fmaxf((v.y-mu)*rs*s_g[256+c4*4+1] + s_b[256+c4*4+1], 0.f);
        KV[(c4*4+2)*VPITCH + row] = fmaxf((v.z-mu)*rs*s_g[256+c4*4+2] + s_b[256+c4*4+2], 0.f);
        KV[(c4*4+3)*VPITCH + row] = fmaxf((v.w-mu)*rs*s_g[256+c4*4+3] + s_b[256+c4*4+3], 0.f);
    }
    __syncthreads();
    float acc[2][8] = {};
#pragma unroll 4
    for (int k2 = 0; k2 < MM; k2 += 2) {
        float2 s0 = *(float2*)&Ss[(2*ty+0)*SPITCH + k2];
        float2 s1 = *(float2*)&Ss[(2*ty+1)*SPITCH + k2];
#pragma unroll
        for (int j = 0; j < 8; j++) {
            float2 vv = *(float2*)&KV[(tx + 16*j)*VPITCH + k2];
            acc[0][j] += s0.x*vv.x; acc[0][j] += s0.y*vv.y;
            acc[1][j] += s1.x*vv.x; acc[1][j] += s1.y*vv.y;
        }
    }
#pragma unroll
    for (int i = 0; i < 2; i++) {
        int node = mem[rb*32 + 2*ty + i];
#pragma unroll
        for (int j = 0; j < 8; j++)
            g_att[node*HD + head*DD + tx + 16*j] = acc[i][j];
    }
}

// ============ kernel 3: o1 split-K  (BM=32, BN=128, 2x8, split 8) ========
__global__ __launch_bounds__(256) void k_o1s(const float* __restrict__ Wo1) {
    __shared__ float As[32*34];
    __shared__ float Bs[128*34];
    int m0 = blockIdx.x * 32;
    int sp = blockIdx.y;
    int kbase = sp * 96;
    int tid = threadIdx.x, tx = tid & 15, ty = tid >> 4;
    float acc[2][8] = {};
    for (int cc = 0; cc < 3; cc++) {
        int k0 = kbase + cc*32;
        {
            int row = tid >> 3, c4 = tid & 7;   // 32x8 f4
            float4 v = *(const float4*)&g_att[(m0+row)*HD + k0 + c4*4];
            float* d = &As[row*34 + c4*4];
            d[0]=v.x; d[1]=v.y; d[2]=v.z; d[3]=v.w;
        }
#pragma unroll
        for (int i = 0; i < 4; i++) {
            int lin = tid + i*256;
            int row = lin >> 3, c4 = lin & 7;
            float4 v = *(const float4*)&Wo1[row*HD + k0 + c4*4];
            float* d = &Bs[row*34 + c4*4];
            d[0]=v.x; d[1]=v.y; d[2]=v.z; d[3]=v.w;
        }
        __syncthreads();
#pragma unroll 8
        for (int k = 0; k < 32; k += 2) {
            float2 a[2], b[8];
#pragma unroll
            for (int i = 0; i < 2; i++) a[i] = *(float2*)&As[(ty + 16*i)*34 + k];
#pragma unroll
            for (int j = 0; j < 8; j++) b[j] = *(float2*)&Bs[(tx + 16*j)*34 + k];
#pragma unroll
            for (int i = 0; i < 2; i++)
#pragma unroll
                for (int j = 0; j < 8; j++) {
                    acc[i][j] += a[i].x * b[j].x;
                    acc[i][j] += a[i].y * b[j].y;
                }
        }
        __syncthreads();
    }
#pragma unroll
    for (int i = 0; i < 2; i++)
#pragma unroll
        for (int j = 0; j < 8; j++)
            g_part[sp*(NN*DD) + (m0 + ty + 16*i)*DD + tx + 16*j] = acc[i][j];
}

// ============ kernel 4: tail (reduce+LN -> mid GEMM+LN -> final+res) =====
__global__ __launch_bounds__(256) void k_tail(const float* __restrict__ agents,
                                              const float* __restrict__ lanes,
                                              const float* __restrict__ go1,
                                              const float* __restrict__ bo1,
                                              const float* __restrict__ W1,
                                              const float* __restrict__ Wo2,
                                              const float* __restrict__ gn,
                                              const float* __restrict__ bn,
                                              const float* __restrict__ W2,
                                              float* __restrict__ out) {
    __shared__ float nodes_s[16*128];
    __shared__ float buf[16*128];
    __shared__ float Bs[128*33];
    int m0 = blockIdx.x * 16;
    int tid = threadIdx.x, tx = tid & 31, ty = tid >> 5;
    const float* Ab = m0 < NA ? agents + m0*DD : lanes + (m0 - NA)*DD;
#pragma unroll
    for (int i = 0; i < 2; i++) {
        int lin = tid + i*256;
        int row = lin >> 5, c4 = lin & 31;
        float4 v = *(const float4*)&Ab[row*DD + c4*4];
        float* d = &nodes_s[row*128 + c4*4];
        d[0]=v.x; d[1]=v.y; d[2]=v.z; d[3]=v.w;
    }
#pragma unroll
    for (int i = 0; i < 8; i++) {
        int e = tid + i*256;
        float s = 0.f;
#pragma unroll
        for (int sp = 0; sp < NSPLIT; sp++) s += g_part[sp*(NN*DD) + m0*DD + e];
        buf[e] = s;
    }
    __syncthreads();
    {
        int w = tid >> 5, lane = tid & 31;
#pragma unroll
        for (int i = 0; i < 2; i++) {
            int r = 2*w + i;
            float x[4]; float s = 0.f, s2 = 0.f;
#pragma unroll
            for (int e = 0; e < 4; e++) {
                x[e] = buf[r*128 + lane + 32*e];
                s += x[e]; s2 += x[e]*x[e];
            }
#pragma unroll
            for (int o = 16; o > 0; o >>= 1) {
                s  += __shfl_xor_sync(0xffffffffu, s,  o);
                s2 += __shfl_xor_sync(0xffffffffu, s2, o);
            }
            float mu = s*(1.f/DD), var = s2*(1.f/DD) - mu*mu;
            float rstd = rsqrtf(var + 1e-5f);
#pragma unroll
            for (int e = 0; e < 4; e++) {
                int c = lane + 32*e;
                buf[r*128 + c] = fmaxf((x[e]-mu)*rstd*go1[c] + bo1[c], 0.f);
            }
        }
    }
    __syncthreads();
    float acc[2][4] = {};
    for (int cc = 0; cc < 8; cc++) {
        const float* W = cc < 4 ? W1 : Wo2;
        const float* A = cc < 4 ? nodes_s : buf;
        int k0 = (cc & 3) * 32;
#pragma unroll
        for (int i = 0; i < 4; i++) {
            int lin = tid + i*256;
            int row = lin >> 3, c4 = lin & 7;
            float4 v = *(const float4*)&W[row*DD + k0 + c4*4];
            float* d = &Bs[row*33 + c4*4];
            d[0]=v.x; d[1]=v.y; d[2]=v.z; d[3]=v.w;
        }
        __syncthreads();
#pragma unroll 4
        for (int k = 0; k < 32; k++) {
            float a0 = A[(2*ty+0)*128 + k0 + k];
            float a1 = A[(2*ty+1)*128 + k0 + k];
#pragma unroll
            for (int j = 0; j < 4; j++) {
                float bb = Bs[(tx + 32*j)*33 + k];
                acc[0][j] += a0*bb;
                acc[1][j] += a1*bb;
            }
        }
        __syncthreads();
    }
#pragma unroll
    for (int i = 0; i < 2; i++)
#pragma unroll
        for (int j = 0; j < 4; j++)
            buf[(2*ty+i)*128 + tx + 32*j] = acc[i][j];
    __syncthreads();
    {
        int w = tid >> 5, lane = tid & 31;
#pragma unroll
        for (int i = 0; i < 2; i++) {
            int r = 2*w + i;
            float x[4]; float s = 0.f, s2 = 0.f;
#pragma unroll
            for (int e = 0; e < 4; e++) {
                x[e] = buf[r*128 + lane + 32*e];
                s += x[e]; s2 += x[e]*x[e];
            }
#pragma unroll
            for (int o = 16; o > 0; o >>= 1) {
                s  += __shfl_xor_sync(0xffffffffu, s,  o);
                s2 += __shfl_xor_sync(0xffffffffu, s2, o);
            }
            float mu = s*(1.f/DD), var = s2*(1.f/DD) - mu*mu;
            float rstd = rsqrtf(var + 1e-5f);
#pragma unroll
            for (int e = 0; e < 4; e++) {
                int c = lane + 32*e;
                buf[r*128 + c] = fmaxf((x[e]-mu)*rstd*gn[c] + bn[c], 0.f);
            }
        }
    }
    __syncthreads();
    float acc2[2][4] = {};
    for (int cc = 0; cc < 4; cc++) {
        int k0 = cc * 32;
#pragma unroll
        for (int i = 0; i < 4; i++) {
            int lin = tid + i*256;
            int row = lin >> 3, c4 = lin & 7;
            float4 v = *(const float4*)&W2[row*DD + k0 + c4*4];
            float* d = &Bs[row*33 + c4*4];
            d[0]=v.x; d[1]=v.y; d[2]=v.z; d[3]=v.w;
        }
        __syncthreads();
#pragma unroll 4
        for (int k = 0; k < 32; k++) {
            float a0 = buf[(2*ty+0)*128 + k0 + k];
            float a1 = buf[(2*ty+1)*128 + k0 + k];
#pragma unroll
            for (int j = 0; j < 4; j++) {
                float bb = Bs[(tx + 32*j)*33 + k];
                acc2[0][j] += a0*bb;
                acc2[1][j] += a1*bb;
            }
        }
        __syncthreads();
    }
#pragma unroll
    for (int i = 0; i < 2; i++) {
        int r = 2*ty + i;
        int orow = g_inv[m0 + r];
#pragma unroll
        for (int j = 0; j < 4; j++) {
            int c = tx + 32*j;
            float x = acc2[i][j] + nodes_s[r*128 + c];
            out[orow*DD + c] = fmaxf(x, 0.f);
        }
    }
}

// ------------------------------------------------------------------------
extern "C" void kernel_launch(void* const* d_in, const int* in_sizes, int n_in,
                              void* d_out, int out_size) {
    const float* agents    = (const float*)d_in[0];
    const int*   agent_ids = (const int*)  d_in[1];
    const float* lanes     = (const float*)d_in[2];
    const int*   lane_ids  = (const int*)  d_in[3];
    const float* Wq  = (const float*)d_in[4];
    const float* gq  = (const float*)d_in[5];
    const float* bq  = (const float*)d_in[6];
    const float* Wk  = (const float*)d_in[7];
    const float* gk  = (const float*)d_in[8];
    const float* bk  = (const float*)d_in[9];
    const float* Wv  = (const float*)d_in[10];
    const float* gv  = (const float*)d_in[11];
    const float* bv  = (const float*)d_in[12];
    const float* Wo1 = (const float*)d_in[13];
    const float* go1 = (const float*)d_in[14];
    const float* bo1 = (const float*)d_in[15];
    const float* Wo2 = (const float*)d_in[16];
    const float* W1  = (const float*)d_in[17];
    const float* gn  = (const float*)d_in[18];
    const float* bn  = (const float*)d_in[19];
    const float* W2  = (const float*)d_in[20];
    float* out = (float*)d_out;

    cudaFuncSetAttribute(k_attn, cudaFuncAttributeMaxDynamicSharedMemorySize, ATTN_SMEM);

    k_qkv <<<dim3(12, 18), 256>>>(agents, lanes, agent_ids, lane_ids, Wq, Wk, Wv);
    k_attn<<<NG*HH*3, 256, ATTN_SMEM>>>(agent_ids, lane_ids, gq, bq, gk, bk, gv, bv);
    k_o1s <<<dim3(24, NSPLIT), 256>>>(Wo1);
    k_tail<<<48, 256>>>(agents, lanes, go1, bo1, W1, Wo2, gn, bn, W2, out);
}